// round 3
// baseline (speedup 1.0000x reference)
#include <cuda_runtime.h>

#define TT 100
#define BB 16384
#define IN 6
#define EH 8
#define SH 24
#define CH 16
#define NC 3
#define RH 16

typedef unsigned long long u64;

// ---- packed f32x2 primitives (Blackwell; per-lane IEEE fp32, bit-identical
//      to scalar fmaf/mul/add, so association & bits are unchanged) ----
__device__ __forceinline__ u64 pack2(float lo, float hi) {
    u64 r; asm("mov.b64 %0,{%1,%2};" : "=l"(r) : "f"(lo), "f"(hi)); return r;
}
__device__ __forceinline__ void unpack2(u64 v, float& lo, float& hi) {
    asm("mov.b64 {%0,%1},%2;" : "=f"(lo), "=f"(hi) : "l"(v));
}
__device__ __forceinline__ u64 fma2(u64 a, u64 b, u64 c) {
    u64 d; asm("fma.rn.f32x2 %0,%1,%2,%3;" : "=l"(d) : "l"(a), "l"(b), "l"(c)); return d;
}
__device__ __forceinline__ u64 mul2(u64 a, u64 b) {
    u64 d; asm("mul.rn.f32x2 %0,%1,%2;" : "=l"(d) : "l"(a), "l"(b)); return d;
}
__device__ __forceinline__ u64 add2(u64 a, u64 b) {
    u64 d; asm("add.rn.f32x2 %0,%1,%2;" : "=l"(d) : "l"(a), "l"(b)); return d;
}

// snntorch Leaky, reset='subtract', THR=1, BETA=0.9 (bit-exact vs reference).
__device__ __forceinline__ void lif_update(float cur, float& m, float& s) {
    float mold = m;
    m = fmaf(0.9f, m, cur);
    if (mold > 1.0f) m -= 1.0f;
    s = (m > 1.0f) ? 1.0f : 0.0f;
}

// Weights repacked into output-pairs, resident in shared memory.
// Row byte-sizes are all multiples of 16 -> ulonglong2 (LDS.128) loads valid.
struct Smem {
    u64   Wec[EH / 2][IN];     // (W[2o][i], W[2o+1][i])
    u64   Wer[EH / 2][IN];
    u64   Ws [SH / 2][2 * EH];
    u64   Wch[CH / 2][SH];
    u64   Wrh[RH / 2][SH];
    u64   Wco01[CH];           // rows 0,1 of Wco paired
    float Wco2[CH];            // row 2 scalar
    float Wro[RH];
    float bec[EH], ber[EH], bs[SH], bch[CH], bco[NC], brh[RH], bro;
};

__global__ void __launch_bounds__(128)
snn_kernel(const float* __restrict__ x,
           const float* __restrict__ We_c, const float* __restrict__ be_c,
           const float* __restrict__ We_r, const float* __restrict__ be_r,
           const float* __restrict__ Wsp,  const float* __restrict__ bsp,
           const float* __restrict__ Wchp, const float* __restrict__ bchp,
           const float* __restrict__ Wcop, const float* __restrict__ bcop,
           const float* __restrict__ Wrhp, const float* __restrict__ brhp,
           const float* __restrict__ Wrop, const float* __restrict__ brop,
           float* __restrict__ out)
{
    __shared__ __align__(16) Smem sm;
    const int tid = threadIdx.x;

    // ---- cooperative repack of weights into smem pairs ----
    for (int idx = tid; idx < (EH / 2) * IN; idx += 128) {
        int o = idx / IN, i = idx % IN;
        sm.Wec[o][i] = pack2(We_c[(2 * o) * IN + i], We_c[(2 * o + 1) * IN + i]);
        sm.Wer[o][i] = pack2(We_r[(2 * o) * IN + i], We_r[(2 * o + 1) * IN + i]);
    }
    for (int idx = tid; idx < (SH / 2) * 2 * EH; idx += 128) {
        int o = idx / (2 * EH), i = idx % (2 * EH);
        sm.Ws[o][i] = pack2(Wsp[(2 * o) * 2 * EH + i], Wsp[(2 * o + 1) * 2 * EH + i]);
    }
    for (int idx = tid; idx < (CH / 2) * SH; idx += 128) {
        int o = idx / SH, i = idx % SH;
        sm.Wch[o][i] = pack2(Wchp[(2 * o) * SH + i], Wchp[(2 * o + 1) * SH + i]);
    }
    for (int idx = tid; idx < (RH / 2) * SH; idx += 128) {
        int o = idx / SH, i = idx % SH;
        sm.Wrh[o][i] = pack2(Wrhp[(2 * o) * SH + i], Wrhp[(2 * o + 1) * SH + i]);
    }
    for (int idx = tid; idx < CH; idx += 128) {
        sm.Wco01[idx] = pack2(Wcop[idx], Wcop[CH + idx]);
        sm.Wco2[idx]  = Wcop[2 * CH + idx];
    }
    if (tid < EH) { sm.bec[tid] = be_c[tid]; sm.ber[tid] = be_r[tid]; }
    if (tid < SH) sm.bs[tid]  = bsp[tid];
    if (tid < CH) sm.bch[tid] = bchp[tid];
    if (tid < NC) sm.bco[tid] = bcop[tid];
    if (tid < RH) { sm.brh[tid] = brhp[tid]; sm.Wro[tid] = Wrop[tid]; }
    if (tid == 0) sm.bro = brop[0];
    __syncthreads();

    const int b = blockIdx.x * 128 + tid;

    float m_ec[EH], m_er[EH], m_sh[SH], m_ch[CH], m_co[NC], m_rh[RH], m_ro;
#pragma unroll
    for (int i = 0; i < EH; ++i) { m_ec[i] = 0.f; m_er[i] = 0.f; }
#pragma unroll
    for (int i = 0; i < SH; ++i) m_sh[i] = 0.f;
#pragma unroll
    for (int i = 0; i < CH; ++i) m_ch[i] = 0.f;
#pragma unroll
    for (int i = 0; i < NC; ++i) m_co[i] = 0.f;
#pragma unroll
    for (int i = 0; i < RH; ++i) m_rh[i] = 0.f;
    m_ro = 0.f;

    const size_t TB = (size_t)TT * BB;
    float* const p_mco = out;
    float* const p_sch = out + TB * 3;
    float* const p_mro = out + TB * 19;
    float* const p_srh = out + TB * 20;
    float* const p_ssh = out + TB * 36;
    float* const p_sec = out + TB * 60;
    float* const p_ser = out + TB * 68;

#pragma unroll 1
    for (int t = 0; t < TT; ++t) {
        const size_t r = (size_t)t * BB + b;

        const float2* xp = (const float2*)(x + r * IN);
        const float2 a0 = xp[0], a1 = xp[1], a2 = xp[2];
        const float xv[IN] = {a0.x, a0.y, a1.x, a1.y, a2.x, a2.y};

        // broadcast-pack x once
        u64 xq[IN];
#pragma unroll
        for (int i = 0; i < IN; ++i) xq[i] = pack2(xv[i], xv[i]);

        // ---- encoders: 4 output-pairs x 6 packed fma each ----
        float s_ec[EH], s_er[EH];
#pragma unroll
        for (int op = 0; op < EH / 2; ++op) {
            u64 acc = 0ull;
#pragma unroll
            for (int i = 0; i < IN; ++i) acc = fma2(xq[i], sm.Wec[op][i], acc);
            float a, bq; unpack2(acc, a, bq);
            lif_update(a  + sm.bec[2 * op],     m_ec[2 * op],     s_ec[2 * op]);
            lif_update(bq + sm.bec[2 * op + 1], m_ec[2 * op + 1], s_ec[2 * op + 1]);
        }
#pragma unroll
        for (int op = 0; op < EH / 2; ++op) {
            u64 acc = 0ull;
#pragma unroll
            for (int i = 0; i < IN; ++i) acc = fma2(xq[i], sm.Wer[op][i], acc);
            float a, bq; unpack2(acc, a, bq);
            lif_update(a  + sm.ber[2 * op],     m_er[2 * op],     s_er[2 * op]);
            lif_update(bq + sm.ber[2 * op + 1], m_er[2 * op + 1], s_er[2 * op + 1]);
        }

        // pack concat(s_ec, s_er) broadcasts
        u64 eq[2 * EH];
#pragma unroll
        for (int i = 0; i < EH; ++i) { eq[i] = pack2(s_ec[i], s_ec[i]); eq[EH + i] = pack2(s_er[i], s_er[i]); }

        // ---- shared layer: 12 pairs x 16 (ascending i: concat order) ----
        float s_sh[SH];
#pragma unroll
        for (int op = 0; op < SH / 2; ++op) {
            const ulonglong2* wr = (const ulonglong2*)sm.Ws[op];
            u64 acc = 0ull;
#pragma unroll
            for (int i = 0; i < 2 * EH; i += 2) {
                ulonglong2 w = wr[i / 2];
                acc = fma2(eq[i],     w.x, acc);
                acc = fma2(eq[i + 1], w.y, acc);
            }
            float a, bq; unpack2(acc, a, bq);
            lif_update(a  + sm.bs[2 * op],     m_sh[2 * op],     s_sh[2 * op]);
            lif_update(bq + sm.bs[2 * op + 1], m_sh[2 * op + 1], s_sh[2 * op + 1]);
        }

        // pack s_sh broadcasts (shared by both heads)
        u64 shq[SH];
#pragma unroll
        for (int i = 0; i < SH; ++i) shq[i] = pack2(s_sh[i], s_sh[i]);

        // ---- classification hidden: 8 pairs x 24 ----
        float s_ch[CH];
#pragma unroll
        for (int op = 0; op < CH / 2; ++op) {
            const ulonglong2* wr = (const ulonglong2*)sm.Wch[op];
            u64 acc = 0ull;
#pragma unroll
            for (int i = 0; i < SH; i += 2) {
                ulonglong2 w = wr[i / 2];
                acc = fma2(shq[i],     w.x, acc);
                acc = fma2(shq[i + 1], w.y, acc);
            }
            float a, bq; unpack2(acc, a, bq);
            lif_update(a  + sm.bch[2 * op],     m_ch[2 * op],     s_ch[2 * op]);
            lif_update(bq + sm.bch[2 * op + 1], m_ch[2 * op + 1], s_ch[2 * op + 1]);
        }

        // pack s_ch broadcasts
        u64 chq[CH];
#pragma unroll
        for (int i = 0; i < CH; ++i) chq[i] = pack2(s_ch[i], s_ch[i]);

        // ---- classification output: pair (0,1) packed + row 2 scalar ----
        {
            const ulonglong2* wr = (const ulonglong2*)sm.Wco01;
            u64 acc = 0ull;
#pragma unroll
            for (int i = 0; i < CH; i += 2) {
                ulonglong2 w = wr[i / 2];
                acc = fma2(chq[i],     w.x, acc);
                acc = fma2(chq[i + 1], w.y, acc);
            }
            float a, bq, su; unpack2(acc, a, bq);
            lif_update(a  + sm.bco[0], m_co[0], su);
            lif_update(bq + sm.bco[1], m_co[1], su);
            float acc2 = 0.f;
#pragma unroll
            for (int i = 0; i < CH; ++i) acc2 = fmaf(s_ch[i], sm.Wco2[i], acc2);
            lif_update(acc2 + sm.bco[2], m_co[2], su);
        }

        // ---- regression hidden: packed butterfly tree (identical per-lane
        //      association to the passing scalar version) ----
        float s_rh[RH];
#pragma unroll
        for (int op = 0; op < RH / 2; ++op) {
            const ulonglong2* wr = (const ulonglong2*)sm.Wrh[op];
            u64 p[32];
#pragma unroll
            for (int i = 0; i < SH; i += 2) {
                ulonglong2 w = wr[i / 2];
                p[i]     = mul2(shq[i],     w.x);
                p[i + 1] = mul2(shq[i + 1], w.y);
            }
#pragma unroll
            for (int i = SH; i < 32; ++i) p[i] = 0ull;
#pragma unroll
            for (int s = 16; s >= 1; s >>= 1) {
#pragma unroll
                for (int i = 0; i < s; ++i) p[i] = add2(p[i], p[i + s]);
            }
            float a, bq; unpack2(p[0], a, bq);
            lif_update(a  + sm.brh[2 * op],     m_rh[2 * op],     s_rh[2 * op]);
            lif_update(bq + sm.brh[2 * op + 1], m_rh[2 * op + 1], s_rh[2 * op + 1]);
        }

        // ---- regression output (scalar, sequential — passing) ----
        {
            float acc = 0.f;
#pragma unroll
            for (int i = 0; i < RH; ++i) acc = fmaf(s_rh[i], sm.Wro[i], acc);
            float su;
            lif_update(acc + sm.bro, m_ro, su);
        }

        // ---- stores ----
        p_mco[r * 3 + 0] = m_co[0];
        p_mco[r * 3 + 1] = m_co[1];
        p_mco[r * 3 + 2] = m_co[2];
        {
            float4* q = (float4*)(p_sch + r * 16);
            q[0] = make_float4(s_ch[0],  s_ch[1],  s_ch[2],  s_ch[3]);
            q[1] = make_float4(s_ch[4],  s_ch[5],  s_ch[6],  s_ch[7]);
            q[2] = make_float4(s_ch[8],  s_ch[9],  s_ch[10], s_ch[11]);
            q[3] = make_float4(s_ch[12], s_ch[13], s_ch[14], s_ch[15]);
        }
        p_mro[r] = m_ro;
        {
            float4* q = (float4*)(p_srh + r * 16);
            q[0] = make_float4(s_rh[0],  s_rh[1],  s_rh[2],  s_rh[3]);
            q[1] = make_float4(s_rh[4],  s_rh[5],  s_rh[6],  s_rh[7]);
            q[2] = make_float4(s_rh[8],  s_rh[9],  s_rh[10], s_rh[11]);
            q[3] = make_float4(s_rh[12], s_rh[13], s_rh[14], s_rh[15]);
        }
        {
            float4* q = (float4*)(p_ssh + r * 24);
            q[0] = make_float4(s_sh[0],  s_sh[1],  s_sh[2],  s_sh[3]);
            q[1] = make_float4(s_sh[4],  s_sh[5],  s_sh[6],  s_sh[7]);
            q[2] = make_float4(s_sh[8],  s_sh[9],  s_sh[10], s_sh[11]);
            q[3] = make_float4(s_sh[12], s_sh[13], s_sh[14], s_sh[15]);
            q[4] = make_float4(s_sh[16], s_sh[17], s_sh[18], s_sh[19]);
            q[5] = make_float4(s_sh[20], s_sh[21], s_sh[22], s_sh[23]);
        }
        {
            float4* q = (float4*)(p_sec + r * 8);
            q[0] = make_float4(s_ec[0], s_ec[1], s_ec[2], s_ec[3]);
            q[1] = make_float4(s_ec[4], s_ec[5], s_ec[6], s_ec[7]);
        }
        {
            float4* q = (float4*)(p_ser + r * 8);
            q[0] = make_float4(s_er[0], s_er[1], s_er[2], s_er[3]);
            q[1] = make_float4(s_er[4], s_er[5], s_er[6], s_er[7]);
        }
    }
}

extern "C" void kernel_launch(void* const* d_in, const int* in_sizes, int n_in,
                              void* d_out, int out_size)
{
    snn_kernel<<<BB / 128, 128>>>(
        (const float*)d_in[0],
        (const float*)d_in[1],  (const float*)d_in[2],
        (const float*)d_in[3],  (const float*)d_in[4],
        (const float*)d_in[5],  (const float*)d_in[6],
        (const float*)d_in[7],  (const float*)d_in[8],
        (const float*)d_in[9],  (const float*)d_in[10],
        (const float*)d_in[11], (const float*)d_in[12],
        (const float*)d_in[13], (const float*)d_in[14],
        (float*)d_out);
}

// round 6
// speedup vs baseline: 6.4602x; 6.4602x over previous
#include <cuda_runtime.h>

#define TT 100
#define BB 16384
#define IN 6
#define EH 8
#define SH 24
#define CH 16
#define NC 3
#define RH 16

// Weights in shared memory (scalar float, rows 16B-multiple for float4 LDS).
struct Smem {
    float Wec[EH][8];       // padded 6 -> 8
    float Wer[EH][8];
    float Ws [SH][2 * EH];  // 16 floats/row
    float Wch[CH][SH];      // 24 floats/row (96B, 16B-multiple)
    float Wrh[RH][SH];
    float Wco[NC][CH];
    float Wro[RH];
    float bec[EH], ber[EH], bs[SH], bch[CH], bco[NC], brh[RH], bro;
};

// bit i of m -> exact 0.0f / 1.0f (3 ALU ops, no I2F)
__device__ __forceinline__ float bit2f(unsigned m, int i) {
    return __int_as_float((((int)(m << (31 - i))) >> 31) & 0x3F800000);
}

// snntorch Leaky, reset='subtract', THR=1, BETA=0.9 — bit-exact vs reference.
// Also records the spike bit into `mask`.
__device__ __forceinline__ float lif(float cur, float& m, unsigned& mask, unsigned bit) {
    float mold = m;
    m = fmaf(0.9f, m, cur);
    if (mold > 1.0f) m -= 1.0f;
    bool sp = (m > 1.0f);
    if (sp) mask |= bit;
    return sp ? 1.0f : 0.0f;
}

__global__ void __launch_bounds__(256)
snn_kernel(const float* __restrict__ x,
           const float* __restrict__ We_c, const float* __restrict__ be_c,
           const float* __restrict__ We_r, const float* __restrict__ be_r,
           const float* __restrict__ Wsp,  const float* __restrict__ bsp,
           const float* __restrict__ Wchp, const float* __restrict__ bchp,
           const float* __restrict__ Wcop, const float* __restrict__ bcop,
           const float* __restrict__ Wrhp, const float* __restrict__ brhp,
           const float* __restrict__ Wrop, const float* __restrict__ brop,
           float* __restrict__ out)
{
    __shared__ __align__(16) Smem sm;
    const int tid = threadIdx.x;

    // ---- cooperative weight staging ----
    for (int idx = tid; idx < EH * 8; idx += 256) {
        int o = idx / 8, i = idx % 8;
        sm.Wec[o][i] = (i < IN) ? We_c[o * IN + i] : 0.f;
        sm.Wer[o][i] = (i < IN) ? We_r[o * IN + i] : 0.f;
    }
    for (int idx = tid; idx < SH * 2 * EH; idx += 256) ((float*)sm.Ws)[idx]  = Wsp[idx];
    for (int idx = tid; idx < CH * SH;     idx += 256) ((float*)sm.Wch)[idx] = Wchp[idx];
    for (int idx = tid; idx < RH * SH;     idx += 256) ((float*)sm.Wrh)[idx] = Wrhp[idx];
    for (int idx = tid; idx < NC * CH;     idx += 256) ((float*)sm.Wco)[idx] = Wcop[idx];
    if (tid < RH) { sm.Wro[tid] = Wrop[tid]; sm.brh[tid] = brhp[tid]; }
    if (tid < EH) { sm.bec[tid] = be_c[tid]; sm.ber[tid] = be_r[tid]; }
    if (tid < SH) sm.bs[tid]  = bsp[tid];
    if (tid < CH) sm.bch[tid] = bchp[tid];
    if (tid < NC) sm.bco[tid] = bcop[tid];
    if (tid == 0) sm.bro = brop[0];
    __syncthreads();

    // ---- pairing: lane l <-> lane l^16; role = data offset only ----
    const int lane = tid & 31;
    const int warp = tid >> 5;
    const int role = lane >> 4;                    // 0 or 1
    const int e    = blockIdx.x * 128 + warp * 16 + (lane & 15);
    const int eo4  = role * 4;                     // encoder output base
    const int so12 = role * 12;                    // shared-layer output base
    const int ho8  = role * 8;                     // ch/rh output base

    // membranes (this thread's half)
    float m_ec[4], m_er[4], m_sh[12], m_ch[8], m_rh[8], m_coA, m_coB, m_ro;
#pragma unroll
    for (int i = 0; i < 4; ++i) { m_ec[i] = 0.f; m_er[i] = 0.f; }
#pragma unroll
    for (int i = 0; i < 12; ++i) m_sh[i] = 0.f;
#pragma unroll
    for (int i = 0; i < 8; ++i) { m_ch[i] = 0.f; m_rh[i] = 0.f; }
    m_coA = 0.f; m_coB = 0.f; m_ro = 0.f;

    const size_t TB = (size_t)TT * BB;
    float* const p_mco = out;
    float* const p_sch = out + TB * 3;
    float* const p_mro = out + TB * 19;
    float* const p_srh = out + TB * 20;
    float* const p_ssh = out + TB * 36;
    float* const p_sec = out + TB * 60;
    float* const p_ser = out + TB * 68;

#pragma unroll 1
    for (int t = 0; t < TT; ++t) {
        const size_t r = (size_t)t * BB + e;

        const float2* xp = (const float2*)(x + r * IN);
        const float2 a0 = xp[0], a1 = xp[1], a2 = xp[2];
        const float xv[IN] = {a0.x, a0.y, a1.x, a1.y, a2.x, a2.y};

        // ---- encoders: this thread does ec rows [eo4,eo4+4) and er rows same ----
        float s_ec[4], s_er[4];
        unsigned emask = 0;
#pragma unroll
        for (int k = 0; k < 4; ++k) {
            const int o = eo4 + k;
            float acc = 0.f;
#pragma unroll
            for (int i = 0; i < IN; ++i) acc = fmaf(xv[i], sm.Wec[o][i], acc);
            s_ec[k] = lif(acc + sm.bec[o], m_ec[k], emask, 1u << o);
        }
#pragma unroll
        for (int k = 0; k < 4; ++k) {
            const int o = eo4 + k;
            float acc = 0.f;
#pragma unroll
            for (int i = 0; i < IN; ++i) acc = fmaf(xv[i], sm.Wer[o][i], acc);
            s_er[k] = lif(acc + sm.ber[o], m_er[k], emask, 1u << (8 + o));
        }
        const unsigned efull = emask | __shfl_xor_sync(0xFFFFFFFFu, emask, 16);

        // unpack full 16-input vector (bits 0-7 = s_ec, 8-15 = s_er; concat order)
        float ein[2 * EH];
#pragma unroll
        for (int i = 0; i < 2 * EH; ++i) ein[i] = bit2f(efull, i);

        // ---- shared layer: rows [so12, so12+12), ascending i (bit-exact) ----
        float s_sh[12];
        unsigned shmask = 0;
#pragma unroll
        for (int k = 0; k < 12; ++k) {
            const int o = so12 + k;
            const float4* wr = (const float4*)sm.Ws[o];
            float acc = 0.f;
#pragma unroll
            for (int j = 0; j < 4; ++j) {
                const float4 w = wr[j];
                acc = fmaf(ein[4 * j + 0], w.x, acc);
                acc = fmaf(ein[4 * j + 1], w.y, acc);
                acc = fmaf(ein[4 * j + 2], w.z, acc);
                acc = fmaf(ein[4 * j + 3], w.w, acc);
            }
            s_sh[k] = lif(acc + sm.bs[o], m_sh[k], shmask, 1u << o);
        }
        const unsigned shfull = shmask | __shfl_xor_sync(0xFFFFFFFFu, shmask, 16);

        float shin[SH];
#pragma unroll
        for (int i = 0; i < SH; ++i) shin[i] = bit2f(shfull, i);

        // ---- classification hidden: rows [ho8, ho8+8) ----
        float s_ch[8];
        unsigned chmask = 0;
#pragma unroll
        for (int k = 0; k < 8; ++k) {
            const int o = ho8 + k;
            const float4* wr = (const float4*)sm.Wch[o];
            float acc = 0.f;
#pragma unroll
            for (int j = 0; j < 6; ++j) {
                const float4 w = wr[j];
                acc = fmaf(shin[4 * j + 0], w.x, acc);
                acc = fmaf(shin[4 * j + 1], w.y, acc);
                acc = fmaf(shin[4 * j + 2], w.z, acc);
                acc = fmaf(shin[4 * j + 3], w.w, acc);
            }
            s_ch[k] = lif(acc + sm.bch[o], m_ch[k], chmask, 1u << o);
        }
        const unsigned chfull = chmask | __shfl_xor_sync(0xFFFFFFFFu, chmask, 16);

        // ---- regression hidden: rows [ho8, ho8+8), butterfly tree (bit-exact) ----
        float s_rh[8];
        unsigned rhmask = 0;
#pragma unroll
        for (int k = 0; k < 8; ++k) {
            const int o = ho8 + k;
            const float4* wr = (const float4*)sm.Wrh[o];
            float p[32];
#pragma unroll
            for (int j = 0; j < 6; ++j) {
                const float4 w = wr[j];
                p[4 * j + 0] = shin[4 * j + 0] * w.x;
                p[4 * j + 1] = shin[4 * j + 1] * w.y;
                p[4 * j + 2] = shin[4 * j + 2] * w.z;
                p[4 * j + 3] = shin[4 * j + 3] * w.w;
            }
#pragma unroll
            for (int i = SH; i < 32; ++i) p[i] = 0.f;
#pragma unroll
            for (int s = 16; s >= 1; s >>= 1) {
#pragma unroll
                for (int i = 0; i < s; ++i) p[i] = p[i] + p[i + s];
            }
            s_rh[k] = lif(p[0] + sm.brh[o], m_rh[k], rhmask, 1u << o);
        }
        const unsigned rhfull = rhmask | __shfl_xor_sync(0xFFFFFFFFu, rhmask, 16);

        // ---- small output layers (balanced divergent tail: ~32 FFMA each side) ----
        unsigned dm = 0;
        if (role == 0) {
            // co rows 0,1 over full s_ch (from chfull)
            float c0 = 0.f, c1 = 0.f;
#pragma unroll
            for (int i = 0; i < CH; ++i) {
                const float s = bit2f(chfull, i);
                c0 = fmaf(s, sm.Wco[0][i], c0);
                c1 = fmaf(s, sm.Wco[1][i], c1);
            }
            lif(c0 + sm.bco[0], m_coA, dm, 0u);
            lif(c1 + sm.bco[1], m_coB, dm, 0u);
        } else {
            // co row 2 + regression output
            float c2 = 0.f, ro = 0.f;
#pragma unroll
            for (int i = 0; i < CH; ++i) c2 = fmaf(bit2f(chfull, i), sm.Wco[2][i], c2);
            lif(c2 + sm.bco[2], m_coA, dm, 0u);
#pragma unroll
            for (int i = 0; i < RH; ++i) ro = fmaf(bit2f(rhfull, i), sm.Wro[i], ro);
            lif(ro + sm.bro, m_ro, dm, 0u);
        }

        // ---- stores (each thread stores what it owns) ----
        if (role == 0) {
            p_mco[r * 3 + 0] = m_coA;
            p_mco[r * 3 + 1] = m_coB;
        } else {
            p_mco[r * 3 + 2] = m_coA;
            p_mro[r] = m_ro;
        }
        {
            float4* q = (float4*)(p_sch + r * 16 + ho8);
            q[0] = make_float4(s_ch[0], s_ch[1], s_ch[2], s_ch[3]);
            q[1] = make_float4(s_ch[4], s_ch[5], s_ch[6], s_ch[7]);
        }
        {
            float4* q = (float4*)(p_srh + r * 16 + ho8);
            q[0] = make_float4(s_rh[0], s_rh[1], s_rh[2], s_rh[3]);
            q[1] = make_float4(s_rh[4], s_rh[5], s_rh[6], s_rh[7]);
        }
        {
            float4* q = (float4*)(p_ssh + r * 24 + so12);
            q[0] = make_float4(s_sh[0], s_sh[1], s_sh[2],  s_sh[3]);
            q[1] = make_float4(s_sh[4], s_sh[5], s_sh[6],  s_sh[7]);
            q[2] = make_float4(s_sh[8], s_sh[9], s_sh[10], s_sh[11]);
        }
        {
            float4* q = (float4*)(p_sec + r * 8 + eo4);
            q[0] = make_float4(s_ec[0], s_ec[1], s_ec[2], s_ec[3]);
        }
        {
            float4* q = (float4*)(p_ser + r * 8 + eo4);
            q[0] = make_float4(s_er[0], s_er[1], s_er[2], s_er[3]);
        }
    }
}

extern "C" void kernel_launch(void* const* d_in, const int* in_sizes, int n_in,
                              void* d_out, int out_size)
{
    snn_kernel<<<128, 256>>>(
        (const float*)d_in[0],
        (const float*)d_in[1],  (const float*)d_in[2],
        (const float*)d_in[3],  (const float*)d_in[4],
        (const float*)d_in[5],  (const float*)d_in[6],
        (const float*)d_in[7],  (const float*)d_in[8],
        (const float*)d_in[9],  (const float*)d_in[10],
        (const float*)d_in[11], (const float*)d_in[12],
        (const float*)d_in[13], (const float*)d_in[14],
        (float*)d_out);
}